// round 15
// baseline (speedup 1.0000x reference)
#include <cuda_runtime.h>
#include <cuda_fp16.h>
#include <math.h>
#include <stdint.h>

// Problem constants
#define B_   4
#define L_   2048
#define DIM_ 1024
#define DFF_ 4096
#define NTOK (B_ * L_)            // 8192 rows
#define CS   32                    // conv chunk size
#define NC   (L_ / CS)             // 64 chunks

// -------- scratch (static __device__ — no allocations allowed) --------
__device__ float   g_y  [(size_t)NTOK * DIM_];
__device__ __half  g_h2h[(size_t)NTOK * DIM_];   // LN2 out, fp16
__device__ __half  g_act[(size_t)NTOK * DFF_];   // SiLU out, fp16
__device__ __half  g_w1h[(size_t)DFF_ * DIM_];   // w1^T fp16 [N=4096,K=1024]
__device__ __half  g_w2h[(size_t)DIM_ * DFF_];   // w2^T fp16 [N=1024,K=4096]
__device__ float2  g_stat[NTOK];                 // LN1 (mu, rstd) per row
__device__ float2  g_carry[B_ * DIM_ * NC];      // [b][d][c] layout
__device__ float2  g_zin  [B_ * DIM_ * NC];      // [b][d][c] layout
__device__ float2  g_p    [DIM_];
__device__ float2  g_pinit[DIM_];
__device__ float2  g_p32  [DIM_];
__device__ float2  g_pw   [NC * DIM_];           // p^(c*CS+1) per (c,d)

// ================= helpers =================
__device__ __forceinline__ uint32_t smem_u32(const void* p) {
    return (uint32_t)__cvta_generic_to_shared(p);
}
__device__ __forceinline__ void cp_async16(uint32_t saddr, const void* gptr) {
    asm volatile("cp.async.cg.shared.global [%0], [%1], 16;" :: "r"(saddr), "l"(gptr));
}
#define CP_COMMIT()  asm volatile("cp.async.commit_group;" ::: "memory")
#define CP_WAIT(n)   asm volatile("cp.async.wait_group %0;" :: "n"(n) : "memory")
#define LDSM_X4(r0, r1, r2, r3, addr) \
    asm volatile("ldmatrix.sync.aligned.m8n8.x4.shared.b16 {%0,%1,%2,%3}, [%4];" \
                 : "=r"(r0), "=r"(r1), "=r"(r2), "=r"(r3) : "r"(addr))

// ================= phazor precompute =================
__global__ void phazor_prep(const float* __restrict__ phazor,
                            const float* __restrict__ phazor_init) {
    int d = blockIdx.x * 256 + threadIdx.x;
    if (d >= DIM_) return;
    float pr = phazor[2 * d], pim = phazor[2 * d + 1];
    float pa = sqrtf(pr * pr + pim * pim);
    float s = expf(-pa) / pa;
    float2 p = make_float2(pr * s, pim * s);
    g_p[d] = p;
    g_pinit[d] = make_float2(phazor_init[2 * d], phazor_init[2 * d + 1]);
    float2 q = p;                              // p^32 via 5 squarings
    #pragma unroll
    for (int i = 0; i < 5; i++) {
        float nr = q.x * q.x - q.y * q.y;
        q.y = 2.f * q.x * q.y;
        q.x = nr;
    }
    g_p32[d] = q;
    float2 pw = p;                             // pw[c] = p^(c*CS + 1)
    for (int c = 0; c < NC; c++) {
        g_pw[c * DIM_ + d] = pw;
        float nr = pw.x * q.x - pw.y * q.y;
        pw.y = pw.x * q.y + pw.y * q.x;
        pw.x = nr;
    }
}

// ========== conv phase1 (fused LN1 stats + scan carry) ==========
__global__ void conv_phase1(const float* __restrict__ x, const float* __restrict__ lng,
                            const float* __restrict__ lnb) {
    __shared__ float2 sh_stat[CS];
    int b = blockIdx.x >> 6, c = blockIdx.x & 63;
    int tid = threadIdx.x;
    int row0 = b * L_ + c * CS;

    {
        int j = tid >> 5, lane = tid & 31;
        const float4* xr = (const float4*)(x + (size_t)(row0 + j) * DIM_);
        float s = 0.f, ss = 0.f;
        #pragma unroll
        for (int i = 0; i < 8; i++) {
            float4 v = xr[lane + 32 * i];
            s  += v.x + v.y + v.z + v.w;
            ss += v.x * v.x + v.y * v.y + v.z * v.z + v.w * v.w;
        }
        #pragma unroll
        for (int o = 16; o > 0; o >>= 1) {
            s  += __shfl_xor_sync(0xffffffffu, s, o);
            ss += __shfl_xor_sync(0xffffffffu, ss, o);
        }
        if (lane == 0) {
            float mu = s * (1.f / DIM_);
            float var = ss * (1.f / DIM_) - mu * mu;
            float2 st = make_float2(mu, rsqrtf(var + 1e-5f));
            sh_stat[j] = st;
            g_stat[row0 + j] = st;
        }
    }
    __syncthreads();

    int d = tid;
    float2 p = g_p[d];
    float gd = lng[d], bd = lnb[d];
    float zr = 0.f, zi = 0.f;
    const float* xp = x + (size_t)row0 * DIM_ + d;
    #pragma unroll 8
    for (int j = 0; j < CS; j++) {
        float2 st = sh_stat[j];
        float hv = (xp[(size_t)j * DIM_] - st.x) * st.y * gd + bd;
        float nr = p.x * zr - p.y * zi + hv;
        zi = p.x * zi + p.y * zr;
        zr = nr;
    }
    g_carry[((size_t)b * DIM_ + d) * NC + c] = make_float2(zr, zi);
}

// ========== conv phase2: warp-parallel affine scan (coalesced layout) ======
__global__ void conv_phase2() {
    int wid = threadIdx.x >> 5, lane = threadIdx.x & 31;
    int ci = blockIdx.x * 8 + wid;
    int b = ci >> 10, d = ci & 1023;
    float2 pc = g_p32[d];

    size_t base = ((size_t)b * DIM_ + d) * NC;
    float2 e0 = g_carry[base + 2 * lane];
    float2 e1 = g_carry[base + 2 * lane + 1];

    float mr = pc.x * pc.x - pc.y * pc.y;
    float mi = 2.f * pc.x * pc.y;
    float vr = pc.x * e0.x - pc.y * e0.y + e1.x;
    float vi = pc.x * e0.y + pc.y * e0.x + e1.y;

    #pragma unroll
    for (int o = 1; o < 32; o <<= 1) {
        float pmr = __shfl_up_sync(0xffffffffu, mr, o);
        float pmi = __shfl_up_sync(0xffffffffu, mi, o);
        float pvr = __shfl_up_sync(0xffffffffu, vr, o);
        float pvi = __shfl_up_sync(0xffffffffu, vi, o);
        if (lane >= o) {
            float nvr = mr * pvr - mi * pvi + vr;
            float nvi = mr * pvi + mi * pvr + vi;
            float nmr = mr * pmr - mi * pmi;
            float nmi = mr * pmi + mi * pmr;
            vr = nvr; vi = nvi; mr = nmr; mi = nmi;
        }
    }

    float zvr = __shfl_up_sync(0xffffffffu, vr, 1);
    float zvi = __shfl_up_sync(0xffffffffu, vi, 1);
    if (lane == 0) { zvr = 0.f; zvi = 0.f; }
    g_zin[base + 2 * lane] = make_float2(zvr, zvi);
    float z1r = pc.x * zvr - pc.y * zvi + e0.x;
    float z1i = pc.x * zvi + pc.y * zvr + e0.y;
    g_zin[base + 2 * lane + 1] = make_float2(z1r, z1i);
}

// ========== conv phase3 (scan -> y) + fused LN2 (y -> h2h fp16) ==========
__global__ void conv_phase3(const float* __restrict__ x, const float* __restrict__ lng,
                            const float* __restrict__ lnb,
                            const float* __restrict__ lre, const float* __restrict__ lim,
                            float* __restrict__ y, __half* __restrict__ h2h) {
    __shared__ float2 sh2[CS];
    int b = blockIdx.x >> 6, c = blockIdx.x & 63;
    int tid = threadIdx.x;
    int row0 = b * L_ + c * CS;

    {
        int d = tid;
        float2 p  = g_p[d];
        float2 pi = g_pinit[d];
        float2 pw = g_pw[c * DIM_ + d];
        float2 z  = g_zin[((size_t)b * DIM_ + d) * NC + c];
        float gd = lng[d], bd = lnb[d];
        float pwr = pw.x, pwi = pw.y;
        float lr = lre[b * DIM_ + d], li = lim[b * DIM_ + d];
        size_t base = (size_t)row0 * DIM_ + d;
        #pragma unroll 8
        for (int j = 0; j < CS; j++) {
            float xv = x[base + (size_t)j * DIM_];
            float2 st = g_stat[row0 + j];
            float hv = (xv - st.x) * st.y * gd + bd;
            float nr = p.x * z.x - p.y * z.y + hv;
            z.y = p.x * z.y + p.y * z.x;
            z.x = nr;
            float val = pi.x * z.x - pi.y * z.y + lr * pwr - li * pwi;
            y[base + (size_t)j * DIM_] = val + xv;
            float npr = pwr * p.x - pwi * p.y;
            pwi = pwr * p.y + pwi * p.x;
            pwr = npr;
        }
    }
    __syncthreads();

    int j = tid >> 5, lane = tid & 31;
    const float4* yr = (const float4*)(y + (size_t)(row0 + j) * DIM_);
    {
        float s = 0.f, ss = 0.f;
        #pragma unroll
        for (int i = 0; i < 8; i++) {
            float4 v = yr[lane + 32 * i];
            s  += v.x + v.y + v.z + v.w;
            ss += v.x * v.x + v.y * v.y + v.z * v.z + v.w * v.w;
        }
        #pragma unroll
        for (int o = 16; o > 0; o >>= 1) {
            s  += __shfl_xor_sync(0xffffffffu, s, o);
            ss += __shfl_xor_sync(0xffffffffu, ss, o);
        }
        if (lane == 0) {
            float mu = s * (1.f / DIM_);
            float var = ss * (1.f / DIM_) - mu * mu;
            sh2[j] = make_float2(mu, rsqrtf(var + 1e-5f));
        }
    }
    __syncthreads();

    {
        float2 st = sh2[j];
        float mu = st.x, inv = st.y;
        #pragma unroll
        for (int i = 0; i < 8; i++) {
            float4 v  = yr[lane + 32 * i];
            float4 gv = ((const float4*)lng)[lane + 32 * i];
            float4 bv = ((const float4*)lnb)[lane + 32 * i];
            __half2 h0 = __floats2half2_rn((v.x - mu) * inv * gv.x + bv.x,
                                           (v.y - mu) * inv * gv.y + bv.y);
            __half2 h1 = __floats2half2_rn((v.z - mu) * inv * gv.z + bv.z,
                                           (v.w - mu) * inv * gv.w + bv.w);
            uint2 pk = make_uint2(*(uint32_t*)&h0, *(uint32_t*)&h1);
            *(uint2*)(h2h + (size_t)(row0 + j) * DIM_ + (lane + 32 * i) * 4) = pk;
        }
    }
}

// ======== weight transpose + cast ([K,N] fp32 -> [N,K] fp16) ========
__global__ void transpose_h(const float* __restrict__ in, __half* __restrict__ out,
                            int R, int Ccols) {
    __shared__ float t[32][33];
    int bx = blockIdx.x * 32, by = blockIdx.y * 32;
    int tx = threadIdx.x, ty = threadIdx.y;
    #pragma unroll
    for (int j = 0; j < 32; j += 8)
        t[ty + j][tx] = in[(size_t)(by + ty + j) * Ccols + bx + tx];
    __syncthreads();
    #pragma unroll
    for (int j = 0; j < 32; j += 8)
        out[(size_t)(bx + ty + j) * R + by + tx] = __float2half(t[tx][ty + j]);
}

// ======= fp16 tensor-core GEMM (mma.sync m16n8k16 + ldmatrix) =======
// CTA tile 128x128, 2 CTAs/SM, BK=64, 8 warps (2x4), warp tile 64x32,
// 3-stage cp.async ring. K/N are template params: unrolled x3 mainloop with
// compile-time stage indices and immediate addressing.
// EPI==0: act(half) = silu(acc + bias);  EPI==1: out(f32) = acc + bias + res
#define TBK 64
#define ROW_B 144                        // stride in bytes
#define CTN 128
#define STG_B ((128 + CTN) * ROW_B)      // 36864
#define GEMM_SMEM (3 * STG_B)            // 110592

template <int EPI, int NCOL, int KDIM>
__global__ __launch_bounds__(256, 2) void hgemm(
    const __half* __restrict__ A, const __half* __restrict__ Bt,
    const float* __restrict__ bias, const float* __restrict__ res,
    __half* __restrict__ Ch, float* __restrict__ Cf) {
    constexpr int WNW = CTN / 4;         // 32
    constexpr int NT  = WNW / 8;         // 4
    constexpr int NP  = NT / 2;          // 2
    constexpr int A_B = 128 * ROW_B;
    constexpr int NK  = KDIM / TBK;

    extern __shared__ char smc[];
    int tid = threadIdx.x, wid = tid >> 5, lane = tid & 31;
    int g = lane >> 2, l4 = lane & 3;
    int wm = (wid & 1) * 64;
    int wn = (wid >> 1) * WNW;
    int bm = blockIdx.y * 128, bn = blockIdx.x * CTN;

    int mat = lane >> 3, rr = lane & 7;
    uint32_t aoff[4], boff[NP];
    #pragma unroll
    for (int mt = 0; mt < 4; mt++)
        aoff[mt] = (uint32_t)((wm + mt * 16 + (mat & 1) * 8 + rr) * ROW_B + (mat >> 1) * 16);
    #pragma unroll
    for (int np = 0; np < NP; np++)
        boff[np] = (uint32_t)((wn + np * 16 + (mat >> 1) * 8 + rr) * ROW_B + (mat & 1) * 16);

    // per stage: A 128 rows x 8 chunks; B 128 x 8; 8 chunks per thread
    int lrow = tid >> 3, lkc = tid & 7;
    const __half* gA = A + (size_t)(bm + lrow) * KDIM + lkc * 8;
    const __half* gB = Bt + (size_t)(bn + lrow) * KDIM + lkc * 8;
    uint32_t sAoff = (uint32_t)(lrow * ROW_B + lkc * 16);

    auto load_stage = [&](int s, int k0) {
        uint32_t base = smem_u32(smc) + s * STG_B + sAoff;
        #pragma unroll
        for (int i = 0; i < 4; i++)
            cp_async16(base + i * 32 * ROW_B, gA + (size_t)32 * i * KDIM + k0);
        base += A_B;
        #pragma unroll
        for (int i = 0; i < 4; i++)
            cp_async16(base + i * 32 * ROW_B, gB + (size_t)32 * i * KDIM + k0);
    };

    float acc[4][NT][4];
    #pragma unroll
    for (int i = 0; i < 4; i++)
        #pragma unroll
        for (int j = 0; j < NT; j++)
            #pragma unroll
            for (int r = 0; r < 4; r++) acc[i][j][r] = 0.f;

    load_stage(0, 0);       CP_COMMIT();
    load_stage(1, TBK);     CP_COMMIT();

    for (int kt0 = 0; kt0 < NK; kt0 += 3) {
        #pragma unroll
        for (int u = 0; u < 3; u++) {
            int kt = kt0 + u;
            if (kt >= NK) break;
            if (kt + 1 < NK) CP_WAIT(1); else CP_WAIT(0);
            __syncthreads();
            if (kt + 2 < NK) load_stage((u + 2) % 3, (kt + 2) * TBK);
            CP_COMMIT();
            uint32_t sa = smem_u32(smc) + u * STG_B;   // stage index compile-time
            uint32_t sb = sa + A_B;
            #pragma unroll
            for (int ks = 0; ks < TBK; ks += 16) {
                uint32_t af[4][4], bf[NT][2];
                #pragma unroll
                for (int mt = 0; mt < 4; mt++)
                    LDSM_X4(af[mt][0], af[mt][1], af[mt][2], af[mt][3],
                            sa + aoff[mt] + ks * 2);
                #pragma unroll
                for (int np = 0; np < NP; np++)
                    LDSM_X4(bf[2 * np][0], bf[2 * np][1], bf[2 * np + 1][0], bf[2 * np + 1][1],
                            sb + boff[np] + ks * 2);
                #pragma unroll
                for (int mt = 0; mt < 4; mt++)
                    #pragma unroll
                    for (int nt = 0; nt < NT; nt++) {
                        asm volatile(
                            "mma.sync.aligned.m16n8k16.row.col.f32.f16.f16.f32 "
                            "{%0,%1,%2,%3}, {%4,%5,%6,%7}, {%8,%9}, {%0,%1,%2,%3};"
                            : "+f"(acc[mt][nt][0]), "+f"(acc[mt][nt][1]),
                              "+f"(acc[mt][nt][2]), "+f"(acc[mt][nt][3])
                            : "r"(af[mt][0]), "r"(af[mt][1]), "r"(af[mt][2]), "r"(af[mt][3]),
                              "r"(bf[nt][0]), "r"(bf[nt][1]));
                    }
            }
        }
    }

    // ---- epilogue ----
    #pragma unroll
    for (int mt = 0; mt < 4; mt++) {
        int r0 = bm + wm + mt * 16 + g;
        #pragma unroll
        for (int nt = 0; nt < NT; nt++) {
            int col = bn + wn + nt * 8 + 2 * l4;
            float bv0 = bias[col], bv1 = bias[col + 1];
            #pragma unroll
            for (int h = 0; h < 2; h++) {
                int row = r0 + h * 8;
                size_t off = (size_t)row * NCOL + col;
                float v0 = acc[mt][nt][2 * h + 0] + bv0;
                float v1 = acc[mt][nt][2 * h + 1] + bv1;
                if (EPI == 0) {
                    v0 = v0 / (1.f + __expf(-v0));
                    v1 = v1 / (1.f + __expf(-v1));
                    __half2 hv = __floats2half2_rn(v0, v1);
                    *(__half2*)&Ch[off] = hv;
                } else {
                    v0 += res[off];
                    v1 += res[off + 1];
                    *(float2*)&Cf[off] = make_float2(v0, v1);
                }
            }
        }
    }
}

// ================= launch =================
extern "C" void kernel_launch(void* const* d_in, const int* in_sizes, int n_in,
                              void* d_out, int out_size) {
    const float* x      = (const float*)d_in[0];
    const float* ln_g   = (const float*)d_in[1];
    const float* ln_b   = (const float*)d_in[2];
    const float* phazor = (const float*)d_in[3];
    const float* phinit = (const float*)d_in[4];
    const float* w1     = (const float*)d_in[5];
    const float* b1     = (const float*)d_in[6];
    const float* w2     = (const float*)d_in[7];
    const float* b2     = (const float*)d_in[8];
    const float* lre    = (const float*)d_in[9];
    const float* lim    = (const float*)d_in[10];
    float* out = (float*)d_out;

    float *y;
    __half *h2h, *act, *w1h, *w2h;
    cudaGetSymbolAddress((void**)&y,   g_y);
    cudaGetSymbolAddress((void**)&h2h, g_h2h);
    cudaGetSymbolAddress((void**)&act, g_act);
    cudaGetSymbolAddress((void**)&w1h, g_w1h);
    cudaGetSymbolAddress((void**)&w2h, g_w2h);

    cudaFuncSetAttribute((hgemm<0, DFF_, DIM_>), cudaFuncAttributeMaxDynamicSharedMemorySize, GEMM_SMEM);
    cudaFuncSetAttribute((hgemm<1, DIM_, DFF_>), cudaFuncAttributeMaxDynamicSharedMemorySize, GEMM_SMEM);

    // side stream for the w1 transpose (overlaps the conv chain) and the w2
    // transpose (overlaps hgemm1). Objects persist — bounded leak; destroying
    // capture-referenced objects mid-capture is illegal.
    cudaStream_t s2;
    cudaStreamCreateWithFlags(&s2, cudaStreamNonBlocking);
    cudaEvent_t evRoot, evT1, evT2;
    cudaEventCreateWithFlags(&evRoot, cudaEventDisableTiming);
    cudaEventCreateWithFlags(&evT1,   cudaEventDisableTiming);
    cudaEventCreateWithFlags(&evT2,   cudaEventDisableTiming);

    cudaEventRecord(evRoot, 0);
    cudaStreamWaitEvent(s2, evRoot, 0);

    transpose_h<<<dim3(DFF_ / 32, DIM_ / 32), dim3(32, 8), 0, s2>>>(w1, w1h, DIM_, DFF_);
    cudaEventRecord(evT1, s2);

    phazor_prep<<<DIM_ / 256, 256>>>(phazor, phinit);
    conv_phase1<<<B_ * NC, DIM_>>>(x, ln_g, ln_b);
    conv_phase2<<<(B_ * DIM_) / 8, 256>>>();
    conv_phase3<<<B_ * NC, DIM_>>>(x, ln_g, ln_b, lre, lim, y, h2h);

    cudaStreamWaitEvent(0, evT1, 0);
    dim3 g1(DFF_ / CTN, NTOK / 128);   // 32 x 64
    hgemm<0, DFF_, DIM_><<<g1, 256, GEMM_SMEM>>>(h2h, w1h, b1, nullptr, act, nullptr);

    transpose_h<<<dim3(DIM_ / 32, DFF_ / 32), dim3(32, 8), 0, s2>>>(w2, w2h, DFF_, DIM_);
    cudaEventRecord(evT2, s2);

    cudaStreamWaitEvent(0, evT2, 0);
    dim3 g2(DIM_ / CTN, NTOK / 128);   // 8 x 64
    hgemm<1, DIM_, DFF_><<<g2, 256, GEMM_SMEM>>>(act, w2h, b2, y, nullptr, out);
}

// round 16
// speedup vs baseline: 1.0164x; 1.0164x over previous
#include <cuda_runtime.h>
#include <cuda_fp16.h>
#include <math.h>
#include <stdint.h>

// Problem constants
#define B_   4
#define L_   2048
#define DIM_ 1024
#define DFF_ 4096
#define NTOK (B_ * L_)            // 8192 rows
#define CS   32                    // conv chunk size
#define NC   (L_ / CS)             // 64 chunks

// -------- scratch (static __device__ — no allocations allowed) --------
__device__ float   g_y  [(size_t)NTOK * DIM_];
__device__ __half  g_h2h[(size_t)NTOK * DIM_];   // LN2 out, fp16
__device__ __half  g_act[(size_t)NTOK * DFF_];   // SiLU out, fp16
__device__ __half  g_w1h[(size_t)DFF_ * DIM_];   // w1^T fp16 [N=4096,K=1024]
__device__ __half  g_w2h[(size_t)DIM_ * DFF_];   // w2^T fp16 [N=1024,K=4096]
__device__ float2  g_stat[NTOK];                 // LN1 (mu, rstd) per row
__device__ float2  g_carry[B_ * DIM_ * NC];      // [b][d][c] layout (coalesced p2)
__device__ float2  g_zin  [B_ * DIM_ * NC];      // [b][d][c] layout
__device__ float2  g_p    [DIM_];
__device__ float2  g_pinit[DIM_];
__device__ float2  g_p32  [DIM_];
__device__ float2  g_pw   [NC * DIM_];           // p^(c*CS+1) per (c,d)

// ================= helpers =================
__device__ __forceinline__ uint32_t smem_u32(const void* p) {
    return (uint32_t)__cvta_generic_to_shared(p);
}
__device__ __forceinline__ void cp_async16(uint32_t saddr, const void* gptr) {
    asm volatile("cp.async.cg.shared.global [%0], [%1], 16;" :: "r"(saddr), "l"(gptr));
}
#define CP_COMMIT()  asm volatile("cp.async.commit_group;" ::: "memory")
#define CP_WAIT(n)   asm volatile("cp.async.wait_group %0;" :: "n"(n) : "memory")
#define LDSM_X4(r0, r1, r2, r3, addr) \
    asm volatile("ldmatrix.sync.aligned.m8n8.x4.shared.b16 {%0,%1,%2,%3}, [%4];" \
                 : "=r"(r0), "=r"(r1), "=r"(r2), "=r"(r3) : "r"(addr))

// ================= phazor precompute =================
__global__ void phazor_prep(const float* __restrict__ phazor,
                            const float* __restrict__ phazor_init) {
    int d = blockIdx.x * 256 + threadIdx.x;
    if (d >= DIM_) return;
    float pr = phazor[2 * d], pim = phazor[2 * d + 1];
    float pa = sqrtf(pr * pr + pim * pim);
    float s = expf(-pa) / pa;
    float2 p = make_float2(pr * s, pim * s);
    g_p[d] = p;
    g_pinit[d] = make_float2(phazor_init[2 * d], phazor_init[2 * d + 1]);
    float2 q = p;                              // p^32 via 5 squarings
    #pragma unroll
    for (int i = 0; i < 5; i++) {
        float nr = q.x * q.x - q.y * q.y;
        q.y = 2.f * q.x * q.y;
        q.x = nr;
    }
    g_p32[d] = q;
    float2 pw = p;                             // pw[c] = p^(c*CS + 1)
    for (int c = 0; c < NC; c++) {
        g_pw[c * DIM_ + d] = pw;
        float nr = pw.x * q.x - pw.y * q.y;
        pw.y = pw.x * q.y + pw.y * q.x;
        pw.x = nr;
    }
}

// ========== conv phase1 (fused LN1 stats + scan carry) ==========
__global__ void conv_phase1(const float* __restrict__ x, const float* __restrict__ lng,
                            const float* __restrict__ lnb) {
    __shared__ float2 sh_stat[CS];
    int b = blockIdx.x >> 6, c = blockIdx.x & 63;
    int tid = threadIdx.x;
    int row0 = b * L_ + c * CS;

    {
        int j = tid >> 5, lane = tid & 31;
        const float4* xr = (const float4*)(x + (size_t)(row0 + j) * DIM_);
        float s = 0.f, ss = 0.f;
        #pragma unroll
        for (int i = 0; i < 8; i++) {
            float4 v = xr[lane + 32 * i];
            s  += v.x + v.y + v.z + v.w;
            ss += v.x * v.x + v.y * v.y + v.z * v.z + v.w * v.w;
        }
        #pragma unroll
        for (int o = 16; o > 0; o >>= 1) {
            s  += __shfl_xor_sync(0xffffffffu, s, o);
            ss += __shfl_xor_sync(0xffffffffu, ss, o);
        }
        if (lane == 0) {
            float mu = s * (1.f / DIM_);
            float var = ss * (1.f / DIM_) - mu * mu;
            float2 st = make_float2(mu, rsqrtf(var + 1e-5f));
            sh_stat[j] = st;
            g_stat[row0 + j] = st;
        }
    }
    __syncthreads();

    int d = tid;
    float2 p = g_p[d];
    float gd = lng[d], bd = lnb[d];
    float zr = 0.f, zi = 0.f;
    const float* xp = x + (size_t)row0 * DIM_ + d;
    #pragma unroll 8
    for (int j = 0; j < CS; j++) {
        float2 st = sh_stat[j];
        float hv = (xp[(size_t)j * DIM_] - st.x) * st.y * gd + bd;
        float nr = p.x * zr - p.y * zi + hv;
        zi = p.x * zi + p.y * zr;
        zr = nr;
    }
    g_carry[((size_t)b * DIM_ + d) * NC + c] = make_float2(zr, zi);
}

// ========== conv phase2: warp-parallel affine scan (coalesced layout) ======
__global__ void conv_phase2() {
    int wid = threadIdx.x >> 5, lane = threadIdx.x & 31;
    int ci = blockIdx.x * 8 + wid;
    int b = ci >> 10, d = ci & 1023;
    float2 pc = g_p32[d];

    size_t base = ((size_t)b * DIM_ + d) * NC;
    float2 e0 = g_carry[base + 2 * lane];
    float2 e1 = g_carry[base + 2 * lane + 1];

    float mr = pc.x * pc.x - pc.y * pc.y;
    float mi = 2.f * pc.x * pc.y;
    float vr = pc.x * e0.x - pc.y * e0.y + e1.x;
    float vi = pc.x * e0.y + pc.y * e0.x + e1.y;

    #pragma unroll
    for (int o = 1; o < 32; o <<= 1) {
        float pmr = __shfl_up_sync(0xffffffffu, mr, o);
        float pmi = __shfl_up_sync(0xffffffffu, mi, o);
        float pvr = __shfl_up_sync(0xffffffffu, vr, o);
        float pvi = __shfl_up_sync(0xffffffffu, vi, o);
        if (lane >= o) {
            float nvr = mr * pvr - mi * pvi + vr;
            float nvi = mr * pvi + mi * pvr + vi;
            float nmr = mr * pmr - mi * pmi;
            float nmi = mr * pmi + mi * pmr;
            vr = nvr; vi = nvi; mr = nmr; mi = nmi;
        }
    }

    float zvr = __shfl_up_sync(0xffffffffu, vr, 1);
    float zvi = __shfl_up_sync(0xffffffffu, vi, 1);
    if (lane == 0) { zvr = 0.f; zvi = 0.f; }
    g_zin[base + 2 * lane] = make_float2(zvr, zvi);
    float z1r = pc.x * zvr - pc.y * zvi + e0.x;
    float z1i = pc.x * zvi + pc.y * zvr + e0.y;
    g_zin[base + 2 * lane + 1] = make_float2(z1r, z1i);
}

// ========== conv phase3 (scan -> y) + fused LN2 (y -> h2h fp16) ==========
__global__ void conv_phase3(const float* __restrict__ x, const float* __restrict__ lng,
                            const float* __restrict__ lnb,
                            const float* __restrict__ lre, const float* __restrict__ lim,
                            float* __restrict__ y, __half* __restrict__ h2h) {
    __shared__ float2 sh2[CS];
    int b = blockIdx.x >> 6, c = blockIdx.x & 63;
    int tid = threadIdx.x;
    int row0 = b * L_ + c * CS;

    {
        int d = tid;
        float2 p  = g_p[d];
        float2 pi = g_pinit[d];
        float2 pw = g_pw[c * DIM_ + d];
        float2 z  = g_zin[((size_t)b * DIM_ + d) * NC + c];
        float gd = lng[d], bd = lnb[d];
        float pwr = pw.x, pwi = pw.y;
        float lr = lre[b * DIM_ + d], li = lim[b * DIM_ + d];
        size_t base = (size_t)row0 * DIM_ + d;
        #pragma unroll 8
        for (int j = 0; j < CS; j++) {
            float xv = x[base + (size_t)j * DIM_];
            float2 st = g_stat[row0 + j];
            float hv = (xv - st.x) * st.y * gd + bd;
            float nr = p.x * z.x - p.y * z.y + hv;
            z.y = p.x * z.y + p.y * z.x;
            z.x = nr;
            float val = pi.x * z.x - pi.y * z.y + lr * pwr - li * pwi;
            y[base + (size_t)j * DIM_] = val + xv;
            float npr = pwr * p.x - pwi * p.y;
            pwi = pwr * p.y + pwi * p.x;
            pwr = npr;
        }
    }
    __syncthreads();

    int j = tid >> 5, lane = tid & 31;
    const float4* yr = (const float4*)(y + (size_t)(row0 + j) * DIM_);
    {
        float s = 0.f, ss = 0.f;
        #pragma unroll
        for (int i = 0; i < 8; i++) {
            float4 v = yr[lane + 32 * i];
            s  += v.x + v.y + v.z + v.w;
            ss += v.x * v.x + v.y * v.y + v.z * v.z + v.w * v.w;
        }
        #pragma unroll
        for (int o = 16; o > 0; o >>= 1) {
            s  += __shfl_xor_sync(0xffffffffu, s, o);
            ss += __shfl_xor_sync(0xffffffffu, ss, o);
        }
        if (lane == 0) {
            float mu = s * (1.f / DIM_);
            float var = ss * (1.f / DIM_) - mu * mu;
            sh2[j] = make_float2(mu, rsqrtf(var + 1e-5f));
        }
    }
    __syncthreads();

    {
        float2 st = sh2[j];
        float mu = st.x, inv = st.y;
        #pragma unroll
        for (int i = 0; i < 8; i++) {
            float4 v  = yr[lane + 32 * i];
            float4 gv = ((const float4*)lng)[lane + 32 * i];
            float4 bv = ((const float4*)lnb)[lane + 32 * i];
            __half2 h0 = __floats2half2_rn((v.x - mu) * inv * gv.x + bv.x,
                                           (v.y - mu) * inv * gv.y + bv.y);
            __half2 h1 = __floats2half2_rn((v.z - mu) * inv * gv.z + bv.z,
                                           (v.w - mu) * inv * gv.w + bv.w);
            uint2 pk = make_uint2(*(uint32_t*)&h0, *(uint32_t*)&h1);
            *(uint2*)(h2h + (size_t)(row0 + j) * DIM_ + (lane + 32 * i) * 4) = pk;
        }
    }
}

// ======== weight transpose + cast ([K,N] fp32 -> [N,K] fp16) ========
__global__ void transpose_h(const float* __restrict__ in, __half* __restrict__ out,
                            int R, int Ccols) {
    __shared__ float t[32][33];
    int bx = blockIdx.x * 32, by = blockIdx.y * 32;
    int tx = threadIdx.x, ty = threadIdx.y;
    #pragma unroll
    for (int j = 0; j < 32; j += 8)
        t[ty + j][tx] = in[(size_t)(by + ty + j) * Ccols + bx + tx];
    __syncthreads();
    #pragma unroll
    for (int j = 0; j < 32; j += 8)
        out[(size_t)(bx + ty + j) * R + by + tx] = __float2half(t[tx][ty + j]);
}

// ======= fp16 tensor-core GEMM (mma.sync m16n8k16 + ldmatrix) =======
// R14 champion version verbatim: CTA tile 128x128, 2 CTAs/SM, BK=64
// (rows 128B data / 144B stride), 8 warps (2x4), warp tile 64x32,
// 3-stage cp.async ring, 1 barrier per k-tile, runtime K/N.
// EPI==0: act(half) = silu(acc + bias);  EPI==1: out(f32) = acc + bias + res
#define TBK 64
#define ROW_B 144                        // stride in bytes
#define CTN 128
#define STG_B ((128 + CTN) * ROW_B)      // 36864
#define GEMM_SMEM (3 * STG_B)            // 110592

template <int EPI>
__global__ __launch_bounds__(256, 2) void hgemm(
    const __half* __restrict__ A, const __half* __restrict__ Bt,
    const float* __restrict__ bias, const float* __restrict__ res,
    __half* __restrict__ Ch, float* __restrict__ Cf, int M, int N, int K) {
    constexpr int WNW = CTN / 4;         // 32
    constexpr int NT  = WNW / 8;         // 4
    constexpr int NP  = NT / 2;          // 2
    constexpr int A_B = 128 * ROW_B;

    extern __shared__ char smc[];
    int tid = threadIdx.x, wid = tid >> 5, lane = tid & 31;
    int g = lane >> 2, l4 = lane & 3;
    int wm = (wid & 1) * 64;
    int wn = (wid >> 1) * WNW;
    int bm = blockIdx.y * 128, bn = blockIdx.x * CTN;
    const int NK = K / TBK;

    int mat = lane >> 3, rr = lane & 7;
    uint32_t aoff[4], boff[NP];
    #pragma unroll
    for (int mt = 0; mt < 4; mt++)
        aoff[mt] = (uint32_t)((wm + mt * 16 + (mat & 1) * 8 + rr) * ROW_B + (mat >> 1) * 16);
    #pragma unroll
    for (int np = 0; np < NP; np++)
        boff[np] = (uint32_t)((wn + np * 16 + (mat >> 1) * 8 + rr) * ROW_B + (mat & 1) * 16);

    // per stage: A 128 rows x 8 chunks = 1024; B 128 x 8 = 1024; 8 per thread
    auto load_stage = [&](int s, int k0) {
        uint32_t base = smem_u32(smc + (size_t)s * STG_B);
        #pragma unroll
        for (int i = 0; i < 4; i++) {
            int c = tid + i * 256;
            int row = c >> 3, kc = c & 7;
            cp_async16(base + row * ROW_B + kc * 16,
                       A + (size_t)(bm + row) * K + k0 + kc * 8);
        }
        uint32_t bb = base + A_B;
        #pragma unroll
        for (int i = 0; i < 4; i++) {
            int c = tid + i * 256;
            int row = c >> 3, kc = c & 7;
            cp_async16(bb + row * ROW_B + kc * 16,
                       Bt + (size_t)(bn + row) * K + k0 + kc * 8);
        }
    };

    float acc[4][NT][4];
    #pragma unroll
    for (int i = 0; i < 4; i++)
        #pragma unroll
        for (int j = 0; j < NT; j++)
            #pragma unroll
            for (int r = 0; r < 4; r++) acc[i][j][r] = 0.f;

    load_stage(0, 0);       CP_COMMIT();
    load_stage(1, TBK);     CP_COMMIT();

    for (int kt = 0; kt < NK; kt++) {
        if (kt + 1 < NK) CP_WAIT(1); else CP_WAIT(0);
        __syncthreads();
        if (kt + 2 < NK) load_stage((kt + 2) % 3, (kt + 2) * TBK);
        CP_COMMIT();
        uint32_t sa = smem_u32(smc + (size_t)(kt % 3) * STG_B);
        uint32_t sb = sa + A_B;
        #pragma unroll
        for (int ks = 0; ks < TBK; ks += 16) {
            uint32_t af[4][4], bf[NT][2];
            #pragma unroll
            for (int mt = 0; mt < 4; mt++)
                LDSM_X4(af[mt][0], af[mt][1], af[mt][2], af[mt][3],
                        sa + aoff[mt] + ks * 2);
            #pragma unroll
            for (int np = 0; np < NP; np++)
                LDSM_X4(bf[2 * np][0], bf[2 * np][1], bf[2 * np + 1][0], bf[2 * np + 1][1],
                        sb + boff[np] + ks * 2);
            #pragma unroll
            for (int mt = 0; mt < 4; mt++)
                #pragma unroll
                for (int nt = 0; nt < NT; nt++) {
                    asm volatile(
                        "mma.sync.aligned.m16n8k16.row.col.f32.f16.f16.f32 "
                        "{%0,%1,%2,%3}, {%4,%5,%6,%7}, {%8,%9}, {%0,%1,%2,%3};"
                        : "+f"(acc[mt][nt][0]), "+f"(acc[mt][nt][1]),
                          "+f"(acc[mt][nt][2]), "+f"(acc[mt][nt][3])
                        : "r"(af[mt][0]), "r"(af[mt][1]), "r"(af[mt][2]), "r"(af[mt][3]),
                          "r"(bf[nt][0]), "r"(bf[nt][1]));
                }
        }
    }

    // ---- epilogue ----
    #pragma unroll
    for (int mt = 0; mt < 4; mt++) {
        int r0 = bm + wm + mt * 16 + g;
        #pragma unroll
        for (int nt = 0; nt < NT; nt++) {
            int col = bn + wn + nt * 8 + 2 * l4;
            float bv0 = bias[col], bv1 = bias[col + 1];
            #pragma unroll
            for (int h = 0; h < 2; h++) {
                int row = r0 + h * 8;
                size_t off = (size_t)row * N + col;
                float v0 = acc[mt][nt][2 * h + 0] + bv0;
                float v1 = acc[mt][nt][2 * h + 1] + bv1;
                if (EPI == 0) {
                    v0 = v0 / (1.f + __expf(-v0));
                    v1 = v1 / (1.f + __expf(-v1));
                    __half2 hv = __floats2half2_rn(v0, v1);
                    *(__half2*)&Ch[off] = hv;
                } else {
                    v0 += res[off];
                    v1 += res[off + 1];
                    *(float2*)&Cf[off] = make_float2(v0, v1);
                }
            }
        }
    }
}

// ================= launch =================
extern "C" void kernel_launch(void* const* d_in, const int* in_sizes, int n_in,
                              void* d_out, int out_size) {
    const float* x      = (const float*)d_in[0];
    const float* ln_g   = (const float*)d_in[1];
    const float* ln_b   = (const float*)d_in[2];
    const float* phazor = (const float*)d_in[3];
    const float* phinit = (const float*)d_in[4];
    const float* w1     = (const float*)d_in[5];
    const float* b1     = (const float*)d_in[6];
    const float* w2     = (const float*)d_in[7];
    const float* b2     = (const float*)d_in[8];
    const float* lre    = (const float*)d_in[9];
    const float* lim    = (const float*)d_in[10];
    float* out = (float*)d_out;

    float *y;
    __half *h2h, *act, *w1h, *w2h;
    cudaGetSymbolAddress((void**)&y,   g_y);
    cudaGetSymbolAddress((void**)&h2h, g_h2h);
    cudaGetSymbolAddress((void**)&act, g_act);
    cudaGetSymbolAddress((void**)&w1h, g_w1h);
    cudaGetSymbolAddress((void**)&w2h, g_w2h);

    cudaFuncSetAttribute(hgemm<0>, cudaFuncAttributeMaxDynamicSharedMemorySize, GEMM_SMEM);
    cudaFuncSetAttribute(hgemm<1>, cudaFuncAttributeMaxDynamicSharedMemorySize, GEMM_SMEM);

    // side stream for the w1 transpose (overlaps the conv chain) and the w2
    // transpose (overlaps hgemm1 — only hgemm2 needs it).
    // (Objects persist — bounded leak; destroying capture-referenced objects
    // mid-capture is illegal.)
    cudaStream_t s2;
    cudaStreamCreateWithFlags(&s2, cudaStreamNonBlocking);
    cudaEvent_t evRoot, evT1, evT2;
    cudaEventCreateWithFlags(&evRoot, cudaEventDisableTiming);
    cudaEventCreateWithFlags(&evT1,   cudaEventDisableTiming);
    cudaEventCreateWithFlags(&evT2,   cudaEventDisableTiming);

    cudaEventRecord(evRoot, 0);
    cudaStreamWaitEvent(s2, evRoot, 0);

    // s2: w1 transpose (overlaps conv chain)
    transpose_h<<<dim3(DFF_ / 32, DIM_ / 32), dim3(32, 8), 0, s2>>>(w1, w1h, DIM_, DFF_);
    cudaEventRecord(evT1, s2);

    // main: phazor precompute -> conv scan
    phazor_prep<<<DIM_ / 256, 256>>>(phazor, phinit);
    conv_phase1<<<B_ * NC, DIM_>>>(x, ln_g, ln_b);
    conv_phase2<<<(B_ * DIM_) / 8, 256>>>();
    conv_phase3<<<B_ * NC, DIM_>>>(x, ln_g, ln_b, lre, lim, y, h2h);

    // main: GEMM1
    cudaStreamWaitEvent(0, evT1, 0);
    dim3 g1(DFF_ / CTN, NTOK / 128);   // 32 x 64
    hgemm<0><<<g1, 256, GEMM_SMEM>>>(h2h, w1h, b1, nullptr, act, nullptr, NTOK, DFF_, DIM_);

    // s2: w2 transpose concurrent with GEMM1
    transpose_h<<<dim3(DIM_ / 32, DFF_ / 32), dim3(32, 8), 0, s2>>>(w2, w2h, DFF_, DIM_);
    cudaEventRecord(evT2, s2);

    // main: GEMM2 (needs act + w2h)
    cudaStreamWaitEvent(0, evT2, 0);
    dim3 g2(DIM_ / CTN, NTOK / 128);   // 8 x 64
    hgemm<1><<<g2, 256, GEMM_SMEM>>>(act, w2h, b2, y, nullptr, out, NTOK, DIM_, DFF_);
}

// round 17
// speedup vs baseline: 1.0801x; 1.0627x over previous
#include <cuda_runtime.h>
#include <cuda_fp16.h>
#include <math.h>
#include <stdint.h>

// Problem constants
#define B_   4
#define L_   2048
#define DIM_ 1024
#define DFF_ 4096
#define NTOK (B_ * L_)            // 8192 rows
#define CS   32                    // conv chunk size
#define NC   (L_ / CS)             // 64 chunks

// -------- scratch (static __device__ — no allocations allowed) --------
__device__ float   g_y  [(size_t)NTOK * DIM_];
__device__ __half  g_h2h[(size_t)NTOK * DIM_];   // LN2 out, fp16
__device__ __half  g_act[(size_t)NTOK * DFF_];   // SiLU out, fp16
__device__ __half  g_w1h[(size_t)DFF_ * DIM_];   // w1^T fp16 [N=4096,K=1024]
__device__ __half  g_w2h[(size_t)DIM_ * DFF_];   // w2^T fp16 [N=1024,K=4096]
__device__ float2  g_stat[NTOK];                 // LN1 (mu, rstd) per row
__device__ float2  g_carry[B_ * DIM_ * NC];      // [b][d][c] layout (coalesced p2)
__device__ float2  g_zin  [B_ * DIM_ * NC];      // [b][d][c] layout
__device__ float2  g_p    [DIM_];
__device__ float2  g_pinit[DIM_];
__device__ float2  g_p32  [DIM_];
__device__ float2  g_pw   [NC * DIM_];           // p^(c*CS+1) per (c,d)

// ================= helpers =================
__device__ __forceinline__ uint32_t smem_u32(const void* p) {
    return (uint32_t)__cvta_generic_to_shared(p);
}
__device__ __forceinline__ void cp_async16(uint32_t saddr, const void* gptr) {
    asm volatile("cp.async.cg.shared.global [%0], [%1], 16;" :: "r"(saddr), "l"(gptr));
}
#define CP_COMMIT()  asm volatile("cp.async.commit_group;" ::: "memory")
#define CP_WAIT(n)   asm volatile("cp.async.wait_group %0;" :: "n"(n) : "memory")
#define LDSM_X4(r0, r1, r2, r3, addr) \
    asm volatile("ldmatrix.sync.aligned.m8n8.x4.shared.b16 {%0,%1,%2,%3}, [%4];" \
                 : "=r"(r0), "=r"(r1), "=r"(r2), "=r"(r3) : "r"(addr))

// ================= phazor precompute =================
__global__ void phazor_prep(const float* __restrict__ phazor,
                            const float* __restrict__ phazor_init) {
    int d = blockIdx.x * 256 + threadIdx.x;
    if (d >= DIM_) return;
    float pr = phazor[2 * d], pim = phazor[2 * d + 1];
    float pa = sqrtf(pr * pr + pim * pim);
    float s = expf(-pa) / pa;
    float2 p = make_float2(pr * s, pim * s);
    g_p[d] = p;
    g_pinit[d] = make_float2(phazor_init[2 * d], phazor_init[2 * d + 1]);
    float2 q = p;                              // p^32 via 5 squarings
    #pragma unroll
    for (int i = 0; i < 5; i++) {
        float nr = q.x * q.x - q.y * q.y;
        q.y = 2.f * q.x * q.y;
        q.x = nr;
    }
    g_p32[d] = q;
    float2 pw = p;                             // pw[c] = p^(c*CS + 1)
    for (int c = 0; c < NC; c++) {
        g_pw[c * DIM_ + d] = pw;
        float nr = pw.x * q.x - pw.y * q.y;
        pw.y = pw.x * q.y + pw.y * q.x;
        pw.x = nr;
    }
}

// ========== conv phase1 (fused LN1 stats + scan carry) ==========
__global__ void conv_phase1(const float* __restrict__ x, const float* __restrict__ lng,
                            const float* __restrict__ lnb) {
    __shared__ float2 sh_stat[CS];
    int b = blockIdx.x >> 6, c = blockIdx.x & 63;
    int tid = threadIdx.x;
    int row0 = b * L_ + c * CS;

    {
        int j = tid >> 5, lane = tid & 31;
        const float4* xr = (const float4*)(x + (size_t)(row0 + j) * DIM_);
        float s = 0.f, ss = 0.f;
        #pragma unroll
        for (int i = 0; i < 8; i++) {
            float4 v = xr[lane + 32 * i];
            s  += v.x + v.y + v.z + v.w;
            ss += v.x * v.x + v.y * v.y + v.z * v.z + v.w * v.w;
        }
        #pragma unroll
        for (int o = 16; o > 0; o >>= 1) {
            s  += __shfl_xor_sync(0xffffffffu, s, o);
            ss += __shfl_xor_sync(0xffffffffu, ss, o);
        }
        if (lane == 0) {
            float mu = s * (1.f / DIM_);
            float var = ss * (1.f / DIM_) - mu * mu;
            float2 st = make_float2(mu, rsqrtf(var + 1e-5f));
            sh_stat[j] = st;
            g_stat[row0 + j] = st;
        }
    }
    __syncthreads();

    int d = tid;
    float2 p = g_p[d];
    float gd = lng[d], bd = lnb[d];
    float zr = 0.f, zi = 0.f;
    const float* xp = x + (size_t)row0 * DIM_ + d;
    #pragma unroll 8
    for (int j = 0; j < CS; j++) {
        float2 st = sh_stat[j];
        float hv = (xp[(size_t)j * DIM_] - st.x) * st.y * gd + bd;
        float nr = p.x * zr - p.y * zi + hv;
        zi = p.x * zi + p.y * zr;
        zr = nr;
    }
    g_carry[((size_t)b * DIM_ + d) * NC + c] = make_float2(zr, zi);
}

// ========== conv phase2: warp-parallel affine scan (coalesced layout) ======
__global__ void conv_phase2() {
    int wid = threadIdx.x >> 5, lane = threadIdx.x & 31;
    int ci = blockIdx.x * 8 + wid;
    int b = ci >> 10, d = ci & 1023;
    float2 pc = g_p32[d];

    size_t base = ((size_t)b * DIM_ + d) * NC;
    float2 e0 = g_carry[base + 2 * lane];
    float2 e1 = g_carry[base + 2 * lane + 1];

    float mr = pc.x * pc.x - pc.y * pc.y;
    float mi = 2.f * pc.x * pc.y;
    float vr = pc.x * e0.x - pc.y * e0.y + e1.x;
    float vi = pc.x * e0.y + pc.y * e0.x + e1.y;

    #pragma unroll
    for (int o = 1; o < 32; o <<= 1) {
        float pmr = __shfl_up_sync(0xffffffffu, mr, o);
        float pmi = __shfl_up_sync(0xffffffffu, mi, o);
        float pvr = __shfl_up_sync(0xffffffffu, vr, o);
        float pvi = __shfl_up_sync(0xffffffffu, vi, o);
        if (lane >= o) {
            float nvr = mr * pvr - mi * pvi + vr;
            float nvi = mr * pvi + mi * pvr + vi;
            float nmr = mr * pmr - mi * pmi;
            float nmi = mr * pmi + mi * pmr;
            vr = nvr; vi = nvi; mr = nmr; mi = nmi;
        }
    }

    float zvr = __shfl_up_sync(0xffffffffu, vr, 1);
    float zvi = __shfl_up_sync(0xffffffffu, vi, 1);
    if (lane == 0) { zvr = 0.f; zvi = 0.f; }
    g_zin[base + 2 * lane] = make_float2(zvr, zvi);
    float z1r = pc.x * zvr - pc.y * zvi + e0.x;
    float z1i = pc.x * zvi + pc.y * zvr + e0.y;
    g_zin[base + 2 * lane + 1] = make_float2(z1r, z1i);
}

// ========== conv phase3 (scan -> y) + fused LN2 (y -> h2h fp16) ==========
__global__ void conv_phase3(const float* __restrict__ x, const float* __restrict__ lng,
                            const float* __restrict__ lnb,
                            const float* __restrict__ lre, const float* __restrict__ lim,
                            float* __restrict__ y, __half* __restrict__ h2h) {
    __shared__ float2 sh2[CS];
    int b = blockIdx.x >> 6, c = blockIdx.x & 63;
    int tid = threadIdx.x;
    int row0 = b * L_ + c * CS;

    {
        int d = tid;
        float2 p  = g_p[d];
        float2 pi = g_pinit[d];
        float2 pw = g_pw[c * DIM_ + d];
        float2 z  = g_zin[((size_t)b * DIM_ + d) * NC + c];
        float gd = lng[d], bd = lnb[d];
        float pwr = pw.x, pwi = pw.y;
        float lr = lre[b * DIM_ + d], li = lim[b * DIM_ + d];
        size_t base = (size_t)row0 * DIM_ + d;
        #pragma unroll 8
        for (int j = 0; j < CS; j++) {
            float xv = x[base + (size_t)j * DIM_];
            float2 st = g_stat[row0 + j];
            float hv = (xv - st.x) * st.y * gd + bd;
            float nr = p.x * z.x - p.y * z.y + hv;
            z.y = p.x * z.y + p.y * z.x;
            z.x = nr;
            float val = pi.x * z.x - pi.y * z.y + lr * pwr - li * pwi;
            y[base + (size_t)j * DIM_] = val + xv;
            float npr = pwr * p.x - pwi * p.y;
            pwi = pwr * p.y + pwi * p.x;
            pwr = npr;
        }
    }
    __syncthreads();

    int j = tid >> 5, lane = tid & 31;
    const float4* yr = (const float4*)(y + (size_t)(row0 + j) * DIM_);
    {
        float s = 0.f, ss = 0.f;
        #pragma unroll
        for (int i = 0; i < 8; i++) {
            float4 v = yr[lane + 32 * i];
            s  += v.x + v.y + v.z + v.w;
            ss += v.x * v.x + v.y * v.y + v.z * v.z + v.w * v.w;
        }
        #pragma unroll
        for (int o = 16; o > 0; o >>= 1) {
            s  += __shfl_xor_sync(0xffffffffu, s, o);
            ss += __shfl_xor_sync(0xffffffffu, ss, o);
        }
        if (lane == 0) {
            float mu = s * (1.f / DIM_);
            float var = ss * (1.f / DIM_) - mu * mu;
            sh2[j] = make_float2(mu, rsqrtf(var + 1e-5f));
        }
    }
    __syncthreads();

    {
        float2 st = sh2[j];
        float mu = st.x, inv = st.y;
        #pragma unroll
        for (int i = 0; i < 8; i++) {
            float4 v  = yr[lane + 32 * i];
            float4 gv = ((const float4*)lng)[lane + 32 * i];
            float4 bv = ((const float4*)lnb)[lane + 32 * i];
            __half2 h0 = __floats2half2_rn((v.x - mu) * inv * gv.x + bv.x,
                                           (v.y - mu) * inv * gv.y + bv.y);
            __half2 h1 = __floats2half2_rn((v.z - mu) * inv * gv.z + bv.z,
                                           (v.w - mu) * inv * gv.w + bv.w);
            uint2 pk = make_uint2(*(uint32_t*)&h0, *(uint32_t*)&h1);
            *(uint2*)(h2h + (size_t)(row0 + j) * DIM_ + (lane + 32 * i) * 4) = pk;
        }
    }
}

// ======== weight transpose + cast ([K,N] fp32 -> [N,K] fp16) ========
__global__ void transpose_h(const float* __restrict__ in, __half* __restrict__ out,
                            int R, int Ccols) {
    __shared__ float t[32][33];
    int bx = blockIdx.x * 32, by = blockIdx.y * 32;
    int tx = threadIdx.x, ty = threadIdx.y;
    #pragma unroll
    for (int j = 0; j < 32; j += 8)
        t[ty + j][tx] = in[(size_t)(by + ty + j) * Ccols + bx + tx];
    __syncthreads();
    #pragma unroll
    for (int j = 0; j < 32; j += 8)
        out[(size_t)(bx + ty + j) * R + by + tx] = __float2half(t[tx][ty + j]);
}

// ======= fp16 tensor-core GEMM (mma.sync m16n8k16 + ldmatrix) =======
// CTA tile 128x128, 2 CTAs/SM, BK=64, 8 warps (2x4), warp tile 64x32,
// 3-stage cp.async ring, 1 barrier per k-tile. Compute-first schedule:
// ks=0 MMAs issue before the next stage's cp.async burst, hiding load
// issue + address math under tensor work.
// EPI==0: act(half) = silu(acc + bias);  EPI==1: out(f32) = acc + bias + res
#define TBK 64
#define ROW_B 144                        // stride in bytes
#define CTN 128
#define STG_B ((128 + CTN) * ROW_B)      // 36864
#define GEMM_SMEM (3 * STG_B)            // 110592

template <int EPI>
__global__ __launch_bounds__(256, 2) void hgemm(
    const __half* __restrict__ A, const __half* __restrict__ Bt,
    const float* __restrict__ bias, const float* __restrict__ res,
    __half* __restrict__ Ch, float* __restrict__ Cf, int M, int N, int K) {
    constexpr int WNW = CTN / 4;         // 32
    constexpr int NT  = WNW / 8;         // 4
    constexpr int NP  = NT / 2;          // 2
    constexpr int A_B = 128 * ROW_B;

    extern __shared__ char smc[];
    int tid = threadIdx.x, wid = tid >> 5, lane = tid & 31;
    int g = lane >> 2, l4 = lane & 3;
    int wm = (wid & 1) * 64;
    int wn = (wid >> 1) * WNW;
    int bm = blockIdx.y * 128, bn = blockIdx.x * CTN;
    const int NK = K / TBK;

    int mat = lane >> 3, rr = lane & 7;
    uint32_t aoff[4], boff[NP];
    #pragma unroll
    for (int mt = 0; mt < 4; mt++)
        aoff[mt] = (uint32_t)((wm + mt * 16 + (mat & 1) * 8 + rr) * ROW_B + (mat >> 1) * 16);
    #pragma unroll
    for (int np = 0; np < NP; np++)
        boff[np] = (uint32_t)((wn + np * 16 + (mat >> 1) * 8 + rr) * ROW_B + (mat & 1) * 16);

    auto load_stage = [&](int s, int k0) {
        uint32_t base = smem_u32(smc + (size_t)s * STG_B);
        #pragma unroll
        for (int i = 0; i < 4; i++) {
            int c = tid + i * 256;
            int row = c >> 3, kc = c & 7;
            cp_async16(base + row * ROW_B + kc * 16,
                       A + (size_t)(bm + row) * K + k0 + kc * 8);
        }
        uint32_t bb = base + A_B;
        #pragma unroll
        for (int i = 0; i < 4; i++) {
            int c = tid + i * 256;
            int row = c >> 3, kc = c & 7;
            cp_async16(bb + row * ROW_B + kc * 16,
                       Bt + (size_t)(bn + row) * K + k0 + kc * 8);
        }
    };

    float acc[4][NT][4];
    #pragma unroll
    for (int i = 0; i < 4; i++)
        #pragma unroll
        for (int j = 0; j < NT; j++)
            #pragma unroll
            for (int r = 0; r < 4; r++) acc[i][j][r] = 0.f;

    load_stage(0, 0);       CP_COMMIT();
    load_stage(1, TBK);     CP_COMMIT();

    // fragment-load + MMA for one 16-wide k-slice
    auto compute_ks = [&](uint32_t sa, uint32_t sb, int ks) {
        uint32_t af[4][4], bf[NT][2];
        #pragma unroll
        for (int mt = 0; mt < 4; mt++)
            LDSM_X4(af[mt][0], af[mt][1], af[mt][2], af[mt][3],
                    sa + aoff[mt] + ks * 2);
        #pragma unroll
        for (int np = 0; np < NP; np++)
            LDSM_X4(bf[2 * np][0], bf[2 * np][1], bf[2 * np + 1][0], bf[2 * np + 1][1],
                    sb + boff[np] + ks * 2);
        #pragma unroll
        for (int mt = 0; mt < 4; mt++)
            #pragma unroll
            for (int nt = 0; nt < NT; nt++) {
                asm volatile(
                    "mma.sync.aligned.m16n8k16.row.col.f32.f16.f16.f32 "
                    "{%0,%1,%2,%3}, {%4,%5,%6,%7}, {%8,%9}, {%0,%1,%2,%3};"
                    : "+f"(acc[mt][nt][0]), "+f"(acc[mt][nt][1]),
                      "+f"(acc[mt][nt][2]), "+f"(acc[mt][nt][3])
                    : "r"(af[mt][0]), "r"(af[mt][1]), "r"(af[mt][2]), "r"(af[mt][3]),
                      "r"(bf[nt][0]), "r"(bf[nt][1]));
            }
    };

    for (int kt = 0; kt < NK; kt++) {
        if (kt + 1 < NK) CP_WAIT(1); else CP_WAIT(0);
        __syncthreads();
        uint32_t sa = smem_u32(smc + (size_t)(kt % 3) * STG_B);
        uint32_t sb = sa + A_B;
        // start the tensor pipe immediately on resident data
        compute_ks(sa, sb, 0);
        // issue next stage's loads under the MMA shadow
        if (kt + 2 < NK) load_stage((kt + 2) % 3, (kt + 2) * TBK);
        CP_COMMIT();
        #pragma unroll
        for (int ks = 16; ks < TBK; ks += 16)
            compute_ks(sa, sb, ks);
    }

    // ---- epilogue ----
    #pragma unroll
    for (int mt = 0; mt < 4; mt++) {
        int r0 = bm + wm + mt * 16 + g;
        #pragma unroll
        for (int nt = 0; nt < NT; nt++) {
            int col = bn + wn + nt * 8 + 2 * l4;
            float bv0 = bias[col], bv1 = bias[col + 1];
            #pragma unroll
            for (int h = 0; h < 2; h++) {
                int row = r0 + h * 8;
                size_t off = (size_t)row * N + col;
                float v0 = acc[mt][nt][2 * h + 0] + bv0;
                float v1 = acc[mt][nt][2 * h + 1] + bv1;
                if (EPI == 0) {
                    v0 = v0 / (1.f + __expf(-v0));
                    v1 = v1 / (1.f + __expf(-v1));
                    __half2 hv = __floats2half2_rn(v0, v1);
                    *(__half2*)&Ch[off] = hv;
                } else {
                    v0 += res[off];
                    v1 += res[off + 1];
                    *(float2*)&Cf[off] = make_float2(v0, v1);
                }
            }
        }
    }
}

// ================= launch =================
extern "C" void kernel_launch(void* const* d_in, const int* in_sizes, int n_in,
                              void* d_out, int out_size) {
    const float* x      = (const float*)d_in[0];
    const float* ln_g   = (const float*)d_in[1];
    const float* ln_b   = (const float*)d_in[2];
    const float* phazor = (const float*)d_in[3];
    const float* phinit = (const float*)d_in[4];
    const float* w1     = (const float*)d_in[5];
    const float* b1     = (const float*)d_in[6];
    const float* w2     = (const float*)d_in[7];
    const float* b2     = (const float*)d_in[8];
    const float* lre    = (const float*)d_in[9];
    const float* lim    = (const float*)d_in[10];
    float* out = (float*)d_out;

    float *y;
    __half *h2h, *act, *w1h, *w2h;
    cudaGetSymbolAddress((void**)&y,   g_y);
    cudaGetSymbolAddress((void**)&h2h, g_h2h);
    cudaGetSymbolAddress((void**)&act, g_act);
    cudaGetSymbolAddress((void**)&w1h, g_w1h);
    cudaGetSymbolAddress((void**)&w2h, g_w2h);

    cudaFuncSetAttribute(hgemm<0>, cudaFuncAttributeMaxDynamicSharedMemorySize, GEMM_SMEM);
    cudaFuncSetAttribute(hgemm<1>, cudaFuncAttributeMaxDynamicSharedMemorySize, GEMM_SMEM);

    // side stream for the w1 transpose (overlaps the conv chain) and the w2
    // transpose (overlaps hgemm1 — only hgemm2 needs it).
    // (Objects persist — bounded leak; destroying capture-referenced objects
    // mid-capture is illegal.)
    cudaStream_t s2;
    cudaStreamCreateWithFlags(&s2, cudaStreamNonBlocking);
    cudaEvent_t evRoot, evT1, evT2;
    cudaEventCreateWithFlags(&evRoot, cudaEventDisableTiming);
    cudaEventCreateWithFlags(&evT1,   cudaEventDisableTiming);
    cudaEventCreateWithFlags(&evT2,   cudaEventDisableTiming);

    cudaEventRecord(evRoot, 0);
    cudaStreamWaitEvent(s2, evRoot, 0);

    // s2: w1 transpose (overlaps conv chain)
    transpose_h<<<dim3(DFF_ / 32, DIM_ / 32), dim3(32, 8), 0, s2>>>(w1, w1h, DIM_, DFF_);
    cudaEventRecord(evT1, s2);

    // main: phazor precompute -> conv scan
    phazor_prep<<<DIM_ / 256, 256>>>(phazor, phinit);
    conv_phase1<<<B_ * NC, DIM_>>>(x, ln_g, ln_b);
    conv_phase2<<<(B_ * DIM_) / 8, 256>>>();
    conv_phase3<<<B_ * NC, DIM_>>>(x, ln_g, ln_b, lre, lim, y, h2h);

    // main: GEMM1
    cudaStreamWaitEvent(0, evT1, 0);
    dim3 g1(DFF_ / CTN, NTOK / 128);   // 32 x 64
    hgemm<0><<<g1, 256, GEMM_SMEM>>>(h2h, w1h, b1, nullptr, act, nullptr, NTOK, DFF_, DIM_);

    // s2: w2 transpose concurrent with GEMM1
    transpose_h<<<dim3(DIM_ / 32, DFF_ / 32), dim3(32, 8), 0, s2>>>(w2, w2h, DFF_, DIM_);
    cudaEventRecord(evT2, s2);

    // main: GEMM2 (needs act + w2h)
    cudaStreamWaitEvent(0, evT2, 0);
    dim3 g2(DIM_ / CTN, NTOK / 128);   // 8 x 64
    hgemm<1><<<g2, 256, GEMM_SMEM>>>(act, w2h, b2, y, nullptr, out, NTOK, DIM_, DFF_);
}